// round 4
// baseline (speedup 1.0000x reference)
#include <cuda_runtime.h>
#include <cuda_bf16.h>

#define NN 100000
#define EE 1600000
#define TOT (EE + NN)
#define HID 64
#define NLAYERS 10

// -------- scratch (device globals; no allocation allowed) --------
__device__ int   g_deg[NN];
__device__ float g_dinv[NN];
__device__ int   g_off[NN + 1];
__device__ int   g_cur[NN];
__device__ int2  g_edges[TOT];          // (src, __float_as_int(norm))
__device__ float g_X[2][(size_t)NN * HID];
__device__ float g_XW[(size_t)NN * HID];
__device__ float g_R[(size_t)NN * HID];

// -------- precompute: degrees / norms / CSR --------
__global__ void k_init() {
    int i = blockIdx.x * blockDim.x + threadIdx.x;
    if (i < NN) g_deg[i] = 1;           // self loop
}

__global__ void k_hist(const int* __restrict__ dst) {
    int e = blockIdx.x * blockDim.x + threadIdx.x;
    if (e < EE) atomicAdd(&g_deg[dst[e]], 1);
}

__global__ void k_dinv() {
    int i = blockIdx.x * blockDim.x + threadIdx.x;
    if (i < NN) g_dinv[i] = rsqrtf((float)g_deg[i]);
}

__global__ void k_scan() {
    __shared__ int s[1024];
    const int CH = 98;                  // 1024*98 = 100352 >= NN
    int t = threadIdx.x;
    int beg = t * CH, end = min(beg + CH, NN);
    int sum = 0;
    for (int i = beg; i < end; i++) sum += g_deg[i];
    s[t] = sum;
    __syncthreads();
    for (int d = 1; d < 1024; d <<= 1) {
        int add = (t >= d) ? s[t - d] : 0;
        __syncthreads();
        s[t] += add;
        __syncthreads();
    }
    int run = (t == 0) ? 0 : s[t - 1];
    for (int i = beg; i < end; i++) {
        g_off[i] = run;
        g_cur[i] = run;
        run += g_deg[i];
    }
    if (end == NN && beg < NN) g_off[NN] = run;
}

__global__ void k_fill(const int* __restrict__ src, const int* __restrict__ dst) {
    int i = blockIdx.x * blockDim.x + threadIdx.x;
    if (i >= TOT) return;
    int s, d;
    if (i < EE) { s = src[i]; d = dst[i]; }
    else        { s = i - EE; d = s; }
    int pos = atomicAdd(&g_cur[d], 1);
    float nrm = g_dinv[s] * g_dinv[d];
    g_edges[pos] = make_int2(s, __float_as_int(nrm));
}

// -------- GEMM helpers: block = 64 rows, 256 threads, each thread 4 rows x 4 cols --------

// X0 = tanh(x @ W_emb + b_emb)
__global__ __launch_bounds__(256) void k_embed(const float* __restrict__ Xin,
                                               const float* __restrict__ W,
                                               const float* __restrict__ b) {
    __shared__ float sW[64 * 64];
    __shared__ float sX[64 * 64];
    int tid = threadIdx.x;
    int r0  = blockIdx.x * 64;
    for (int i = tid; i < 1024; i += 256) {
        ((float4*)sW)[i] = ((const float4*)W)[i];
        int row = i >> 4;
        float4 v = (r0 + row < NN) ? ((const float4*)Xin)[(size_t)r0 * 16 + i]
                                   : make_float4(0, 0, 0, 0);
        ((float4*)sX)[i] = v;
    }
    __syncthreads();
    int cg = tid & 15, rg = tid >> 4, row = rg * 4;
    float4 bias = *(const float4*)&b[cg * 4];
    float acc[4][4];
#pragma unroll
    for (int a = 0; a < 4; a++) { acc[a][0] = bias.x; acc[a][1] = bias.y; acc[a][2] = bias.z; acc[a][3] = bias.w; }
#pragma unroll 8
    for (int k = 0; k < 64; k++) {
        float4 w = *(const float4*)&sW[k * 64 + cg * 4];
#pragma unroll
        for (int a = 0; a < 4; a++) {
            float xk = sX[(row + a) * 64 + k];
            acc[a][0] += xk * w.x; acc[a][1] += xk * w.y; acc[a][2] += xk * w.z; acc[a][3] += xk * w.w;
        }
    }
#pragma unroll
    for (int a = 0; a < 4; a++) {
        int r = r0 + row + a;
        if (r < NN) {
            float4 v = make_float4(tanhf(acc[a][0]), tanhf(acc[a][1]), tanhf(acc[a][2]), tanhf(acc[a][3]));
            *(float4*)&g_X[0][(size_t)r * 64 + cg * 4] = v;
        }
    }
}

// XW = X @ W_c ; R = XW @ W_r + b_r
__global__ __launch_bounds__(256) void k_dual(int inbuf,
                                              const float* __restrict__ Wc,
                                              const float* __restrict__ Wr,
                                              const float* __restrict__ br) {
    __shared__ float sW1[64 * 64];
    __shared__ float sW2[64 * 64];
    __shared__ float sX[64 * 64];
    int tid = threadIdx.x;
    int r0  = blockIdx.x * 64;
    const float* Xin = g_X[inbuf];
    for (int i = tid; i < 1024; i += 256) {
        ((float4*)sW1)[i] = ((const float4*)Wc)[i];
        ((float4*)sW2)[i] = ((const float4*)Wr)[i];
        int row = i >> 4;
        float4 v = (r0 + row < NN) ? ((const float4*)Xin)[(size_t)r0 * 16 + i]
                                   : make_float4(0, 0, 0, 0);
        ((float4*)sX)[i] = v;
    }
    __syncthreads();
    int cg = tid & 15, rg = tid >> 4, row = rg * 4;
    float acc[4][4];
#pragma unroll
    for (int a = 0; a < 4; a++) { acc[a][0] = 0.f; acc[a][1] = 0.f; acc[a][2] = 0.f; acc[a][3] = 0.f; }
#pragma unroll 8
    for (int k = 0; k < 64; k++) {
        float4 w = *(const float4*)&sW1[k * 64 + cg * 4];
#pragma unroll
        for (int a = 0; a < 4; a++) {
            float xk = sX[(row + a) * 64 + k];
            acc[a][0] += xk * w.x; acc[a][1] += xk * w.y; acc[a][2] += xk * w.z; acc[a][3] += xk * w.w;
        }
    }
    __syncthreads();
#pragma unroll
    for (int a = 0; a < 4; a++) {
        float4 v = make_float4(acc[a][0], acc[a][1], acc[a][2], acc[a][3]);
        *(float4*)&sX[(row + a) * 64 + cg * 4] = v;
        int r = r0 + row + a;
        if (r < NN) *(float4*)&g_XW[(size_t)r * 64 + cg * 4] = v;
    }
    __syncthreads();
    float4 bias = *(const float4*)&br[cg * 4];
#pragma unroll
    for (int a = 0; a < 4; a++) { acc[a][0] = bias.x; acc[a][1] = bias.y; acc[a][2] = bias.z; acc[a][3] = bias.w; }
#pragma unroll 8
    for (int k = 0; k < 64; k++) {
        float4 w = *(const float4*)&sW2[k * 64 + cg * 4];
#pragma unroll
        for (int a = 0; a < 4; a++) {
            float xk = sX[(row + a) * 64 + k];
            acc[a][0] += xk * w.x; acc[a][1] += xk * w.y; acc[a][2] += xk * w.z; acc[a][3] += xk * w.w;
        }
    }
#pragma unroll
    for (int a = 0; a < 4; a++) {
        int r = r0 + row + a;
        if (r < NN) {
            float4 v = make_float4(acc[a][0], acc[a][1], acc[a][2], acc[a][3]);
            *(float4*)&g_R[(size_t)r * 64 + cg * 4] = v;
        }
    }
}

// Xout = tanh( sum_{e->v} norm * XW[src] + b_c - R[v] )   (warp per node)
__global__ __launch_bounds__(256) void k_agg(const float* __restrict__ bc, int outbuf) {
    int v = blockIdx.x * 8 + (threadIdx.x >> 5);
    if (v >= NN) return;
    int lane = threadIdx.x & 31;
    int beg = g_off[v], end = g_off[v + 1];
    float ax = 0.f, ay = 0.f;
    int i = beg;
    for (; i + 1 < end; i += 2) {
        int2 m0 = g_edges[i];
        int2 m1 = g_edges[i + 1];
        float2 x0 = *(const float2*)&g_XW[(size_t)m0.x * 64 + lane * 2];
        float2 x1 = *(const float2*)&g_XW[(size_t)m1.x * 64 + lane * 2];
        float n0 = __int_as_float(m0.y);
        float n1 = __int_as_float(m1.y);
        ax += n0 * x0.x + n1 * x1.x;
        ay += n0 * x0.y + n1 * x1.y;
    }
    if (i < end) {
        int2 m = g_edges[i];
        float2 xv = *(const float2*)&g_XW[(size_t)m.x * 64 + lane * 2];
        float n = __int_as_float(m.y);
        ax += n * xv.x;
        ay += n * xv.y;
    }
    float2 r = *(const float2*)&g_R[(size_t)v * 64 + lane * 2];
    float2 b = *(const float2*)&bc[lane * 2];
    float2 o = make_float2(tanhf(ax + b.x - r.x), tanhf(ay + b.y - r.y));
    *(float2*)&g_X[outbuf][(size_t)v * 64 + lane * 2] = o;
}

// out = lrelu( lrelu(X @ W1 + b1) @ W2 + b2 )   64 rows/block, 128 threads
__device__ __forceinline__ float lrelu(float v) { return fmaxf(v, 0.01f * v); }

__global__ __launch_bounds__(128) void k_read(const float* __restrict__ W1,
                                              const float* __restrict__ b1,
                                              const float* __restrict__ W2,
                                              const float* __restrict__ b2,
                                              float* __restrict__ out) {
    __shared__ float sX[64 * 64];
    __shared__ float sW1[64 * 32];
    __shared__ float sW2[32 * 32];
    __shared__ float sH[64 * 32];
    int tid = threadIdx.x;
    int r0  = blockIdx.x * 64;
    const float* Xin = g_X[0];
    for (int i = tid; i < 1024; i += 128) {
        int row = i >> 4;
        float4 v = (r0 + row < NN) ? ((const float4*)Xin)[(size_t)r0 * 16 + i]
                                   : make_float4(0, 0, 0, 0);
        ((float4*)sX)[i] = v;
    }
    for (int i = tid; i < 512; i += 128) ((float4*)sW1)[i] = ((const float4*)W1)[i];
    for (int i = tid; i < 256; i += 128) ((float4*)sW2)[i] = ((const float4*)W2)[i];
    __syncthreads();
    int cg = tid & 7, rg = tid >> 3, row = rg * 4;
    float4 bias = *(const float4*)&b1[cg * 4];
    float acc[4][4];
#pragma unroll
    for (int a = 0; a < 4; a++) { acc[a][0] = bias.x; acc[a][1] = bias.y; acc[a][2] = bias.z; acc[a][3] = bias.w; }
#pragma unroll 8
    for (int k = 0; k < 64; k++) {
        float4 w = *(const float4*)&sW1[k * 32 + cg * 4];
#pragma unroll
        for (int a = 0; a < 4; a++) {
            float xk = sX[(row + a) * 64 + k];
            acc[a][0] += xk * w.x; acc[a][1] += xk * w.y; acc[a][2] += xk * w.z; acc[a][3] += xk * w.w;
        }
    }
#pragma unroll
    for (int a = 0; a < 4; a++) {
        float4 v = make_float4(lrelu(acc[a][0]), lrelu(acc[a][1]), lrelu(acc[a][2]), lrelu(acc[a][3]));
        *(float4*)&sH[(row + a) * 32 + cg * 4] = v;
    }
    __syncthreads();
    float4 bias2 = *(const float4*)&b2[cg * 4];
#pragma unroll
    for (int a = 0; a < 4; a++) { acc[a][0] = bias2.x; acc[a][1] = bias2.y; acc[a][2] = bias2.z; acc[a][3] = bias2.w; }
#pragma unroll
    for (int k = 0; k < 32; k++) {
        float4 w = *(const float4*)&sW2[k * 32 + cg * 4];
#pragma unroll
        for (int a = 0; a < 4; a++) {
            float xk = sH[(row + a) * 32 + k];
            acc[a][0] += xk * w.x; acc[a][1] += xk * w.y; acc[a][2] += xk * w.z; acc[a][3] += xk * w.w;
        }
    }
#pragma unroll
    for (int a = 0; a < 4; a++) {
        int r = r0 + row + a;
        if (r < NN) {
            float4 v = make_float4(lrelu(acc[a][0]), lrelu(acc[a][1]), lrelu(acc[a][2]), lrelu(acc[a][3]));
            *(float4*)&out[(size_t)r * 32 + cg * 4] = v;
        }
    }
}

extern "C" void kernel_launch(void* const* d_in, const int* in_sizes, int n_in,
                              void* d_out, int out_size) {
    const float* x     = (const float*)d_in[0];
    const int*   ei    = (const int*)d_in[1];
    const float* W_emb = (const float*)d_in[2];
    const float* b_emb = (const float*)d_in[3];
    const float* W_c   = (const float*)d_in[4];
    const float* b_c   = (const float*)d_in[5];
    const float* W_r   = (const float*)d_in[6];
    const float* b_r   = (const float*)d_in[7];
    const float* W_1   = (const float*)d_in[8];
    const float* b_1   = (const float*)d_in[9];
    const float* W_2   = (const float*)d_in[10];
    const float* b_2   = (const float*)d_in[11];
    float* out = (float*)d_out;

    const int* src = ei;
    const int* dst = ei + EE;

    k_init<<<(NN + 255) / 256, 256>>>();
    k_hist<<<(EE + 255) / 256, 256>>>(dst);
    k_dinv<<<(NN + 255) / 256, 256>>>();
    k_scan<<<1, 1024>>>();
    k_fill<<<(TOT + 255) / 256, 256>>>(src, dst);

    int gemm_blocks = (NN + 63) / 64;
    k_embed<<<gemm_blocks, 256>>>(x, W_emb, b_emb);

    for (int t = 0; t < NLAYERS; t++) {
        k_dual<<<gemm_blocks, 256>>>(t & 1, W_c, W_r, b_r);
        k_agg<<<(NN + 7) / 8, 256>>>(b_c, (t + 1) & 1);
    }

    k_read<<<gemm_blocks, 128>>>(W_1, b_1, W_2, b_2, out);
}